// round 1
// baseline (speedup 1.0000x reference)
#include <cuda_runtime.h>
#include <cuda_bf16.h>
#include <math.h>

// ---------------- problem constants ----------------
#define NN 100000
#define NC 50000
#define EE 400000
#define ND 43
#define CD 2
#define HID 128
#define NH 4
#define CH 32
#define NL 4
#define SLOPE 0.2f
#define LNEPS 1e-5f

// ---------------- device scratch (static, no allocation) ----------------
__device__ float g_xn[(size_t)NN * HID];
__device__ float g_xc[(size_t)NC * HID];
__device__ float g_xl[(size_t)NN * HID];
__device__ float g_xr[(size_t)NN * HID];
__device__ float g_agg[(size_t)NN * HID];
__device__ float g_score[(size_t)EE * NH];
__device__ float g_smax[(size_t)NN * NH];
__device__ float g_den[(size_t)NN * NH];

// ---------------- helpers ----------------
__device__ __forceinline__ void atomicMaxFloat(float* addr, float value) {
    if (value >= 0.0f)
        atomicMax((int*)addr, __float_as_int(value));
    else
        atomicMin((unsigned int*)addr, __float_as_uint(value));
}

// ---------------- fill ----------------
__global__ void fill_kernel(float* __restrict__ p, float v, int n) {
    int i = blockIdx.x * blockDim.x + threadIdx.x;
    if (i < n) p[i] = v;
}

// ---------------- small-K projection: Y[N,128] = X[N,K] @ W[K,128] + b ----------------
__global__ void proj_kernel(const float* __restrict__ X, const float* __restrict__ W,
                            const float* __restrict__ b, float* __restrict__ Y,
                            int N, int K) {
    __shared__ float xs[64];
    int row = blockIdx.x;
    if (row >= N) return;
    int n = threadIdx.x;  // 128 threads
    if (n < K) xs[n] = X[(size_t)row * K + n];
    __syncthreads();
    float acc = b[n];
    for (int k = 0; k < K; k++) acc = fmaf(xs[k], W[k * HID + n], acc);
    Y[(size_t)row * HID + n] = acc;
}

// ---------------- SGEMM: Y[N,128] = X[N,128] @ W[128,128] + b ----------------
// block: 256 threads, tile 64 rows x 128 cols, BK=32, microtile 8x4
__global__ void gemm128_kernel(const float* __restrict__ X, const float* __restrict__ W,
                               const float* __restrict__ bias, float* __restrict__ Y,
                               int N) {
    __shared__ __align__(16) float Xs[64][32];
    __shared__ __align__(16) float Ws[32][128];
    int tid = threadIdx.x;
    int tx = tid & 31;       // col group 0..31 -> cols tx*4..tx*4+3
    int ty = tid >> 5;       // row group 0..7 -> rows ty*8..ty*8+7
    int rowBase = blockIdx.x * 64;

    float acc[8][4];
#pragma unroll
    for (int i = 0; i < 8; i++)
#pragma unroll
        for (int j = 0; j < 4; j++) acc[i][j] = 0.0f;

    for (int k0 = 0; k0 < 128; k0 += 32) {
#pragma unroll
        for (int i = 0; i < 8; i++) {
            int lin = tid + i * 256;
            int r = lin >> 5, k = lin & 31;
            int gr = rowBase + r;
            Xs[r][k] = (gr < N) ? X[(size_t)gr * HID + k0 + k] : 0.0f;
        }
#pragma unroll
        for (int i = 0; i < 16; i++) {
            int lin = tid + i * 256;
            int k = lin >> 7, n = lin & 127;
            Ws[k][n] = W[(k0 + k) * HID + n];
        }
        __syncthreads();
#pragma unroll
        for (int k = 0; k < 32; k++) {
            float4 b4 = *reinterpret_cast<const float4*>(&Ws[k][tx * 4]);
            float a[8];
#pragma unroll
            for (int i = 0; i < 8; i++) a[i] = Xs[ty * 8 + i][k];
#pragma unroll
            for (int i = 0; i < 8; i++) {
                acc[i][0] = fmaf(a[i], b4.x, acc[i][0]);
                acc[i][1] = fmaf(a[i], b4.y, acc[i][1]);
                acc[i][2] = fmaf(a[i], b4.z, acc[i][2]);
                acc[i][3] = fmaf(a[i], b4.w, acc[i][3]);
            }
        }
        __syncthreads();
    }
    float4 bb = *reinterpret_cast<const float4*>(bias + tx * 4);
#pragma unroll
    for (int i = 0; i < 8; i++) {
        int gr = rowBase + ty * 8 + i;
        if (gr < N) {
            float4 o;
            o.x = acc[i][0] + bb.x;
            o.y = acc[i][1] + bb.y;
            o.z = acc[i][2] + bb.z;
            o.w = acc[i][3] + bb.w;
            *reinterpret_cast<float4*>(&Y[(size_t)gr * HID + tx * 4]) = o;
        }
    }
}

// ---------------- edge pass 1: scores + segment max ----------------
// one warp per edge; lane l covers channel l of each of the 4 heads
__global__ void epass1_kernel(const int* __restrict__ src, const int* __restrict__ dst,
                              const float* __restrict__ xl, const float* __restrict__ xr,
                              const float* __restrict__ att,
                              float* __restrict__ score, float* __restrict__ smax, int E) {
    int w = (blockIdx.x * blockDim.x + threadIdx.x) >> 5;
    int l = threadIdx.x & 31;
    if (w >= E) return;
    int s = src[w], d = dst[w];
    const float* pl = xl + (size_t)s * HID;
    const float* pr = xr + (size_t)d * HID;
    float sc0, sc1, sc2, sc3;
    {
        float v;
        v = pl[0 * CH + l] + pr[0 * CH + l]; v = v > 0.0f ? v : SLOPE * v; sc0 = v * att[0 * CH + l];
        v = pl[1 * CH + l] + pr[1 * CH + l]; v = v > 0.0f ? v : SLOPE * v; sc1 = v * att[1 * CH + l];
        v = pl[2 * CH + l] + pr[2 * CH + l]; v = v > 0.0f ? v : SLOPE * v; sc2 = v * att[2 * CH + l];
        v = pl[3 * CH + l] + pr[3 * CH + l]; v = v > 0.0f ? v : SLOPE * v; sc3 = v * att[3 * CH + l];
    }
#pragma unroll
    for (int off = 16; off > 0; off >>= 1) {
        sc0 += __shfl_xor_sync(0xffffffffu, sc0, off);
        sc1 += __shfl_xor_sync(0xffffffffu, sc1, off);
        sc2 += __shfl_xor_sync(0xffffffffu, sc2, off);
        sc3 += __shfl_xor_sync(0xffffffffu, sc3, off);
    }
    if (l < 4) {
        float mine = (l == 0) ? sc0 : (l == 1) ? sc1 : (l == 2) ? sc2 : sc3;
        score[(size_t)w * NH + l] = mine;
        atomicMaxFloat(&smax[(size_t)d * NH + l], mine);
    }
}

// ---------------- edge pass 2: exp + segment sum ----------------
__global__ void epass2_kernel(const int* __restrict__ dst, float* __restrict__ score,
                              const float* __restrict__ smax, float* __restrict__ den, int E4) {
    int i = blockIdx.x * blockDim.x + threadIdx.x;
    if (i >= E4) return;
    int e = i >> 2, h = i & 3;
    int d = dst[e];
    float ex = __expf(score[i] - smax[(size_t)d * NH + h]);
    score[i] = ex;  // now holds exp values
    atomicAdd(&den[(size_t)d * NH + h], ex);
}

// ---------------- edge pass 3: alpha-weighted scatter ----------------
__global__ void epass3_kernel(const int* __restrict__ src, const int* __restrict__ dst,
                              const float* __restrict__ xl, const float* __restrict__ exs,
                              const float* __restrict__ den, float* __restrict__ agg, int E) {
    int w = (blockIdx.x * blockDim.x + threadIdx.x) >> 5;
    int l = threadIdx.x & 31;
    if (w >= E) return;
    int s = src[w], d = dst[w];
    float a0 = exs[(size_t)w * NH + 0] / den[(size_t)d * NH + 0];
    float a1 = exs[(size_t)w * NH + 1] / den[(size_t)d * NH + 1];
    float a2 = exs[(size_t)w * NH + 2] / den[(size_t)d * NH + 2];
    float a3 = exs[(size_t)w * NH + 3] / den[(size_t)d * NH + 3];
    const float* pl = xl + (size_t)s * HID;
    float* pa = agg + (size_t)d * HID;
    atomicAdd(&pa[0 * CH + l], pl[0 * CH + l] * a0);
    atomicAdd(&pa[1 * CH + l], pl[1 * CH + l] * a1);
    atomicAdd(&pa[2 * CH + l], pl[2 * CH + l] * a2);
    atomicAdd(&pa[3 * CH + l], pl[3 * CH + l] * a3);
}

// ---------------- residual + bias + LayerNorm (warp per row) ----------------
__global__ void ln_kernel(float* __restrict__ x, const float* __restrict__ agg,
                          const float* __restrict__ bias, const float* __restrict__ g,
                          const float* __restrict__ b, int N) {
    int w = (blockIdx.x * blockDim.x + threadIdx.x) >> 5;
    int l = threadIdx.x & 31;
    if (w >= N) return;
    float v[4];
    float s = 0.0f;
#pragma unroll
    for (int h = 0; h < 4; h++) {
        size_t idx = (size_t)w * HID + h * CH + l;
        v[h] = x[idx] + agg[idx] + bias[h * CH + l];
        s += v[h];
    }
#pragma unroll
    for (int off = 16; off > 0; off >>= 1) s += __shfl_xor_sync(0xffffffffu, s, off);
    float mu = s * (1.0f / HID);
    float q = 0.0f;
#pragma unroll
    for (int h = 0; h < 4; h++) {
        float dd = v[h] - mu;
        q += dd * dd;
    }
#pragma unroll
    for (int off = 16; off > 0; off >>= 1) q += __shfl_xor_sync(0xffffffffu, q, off);
    float rs = rsqrtf(q * (1.0f / HID) + LNEPS);
#pragma unroll
    for (int h = 0; h < 4; h++) {
        size_t idx = (size_t)w * HID + h * CH + l;
        x[idx] = (v[h] - mu) * rs * g[h * CH + l] + b[h * CH + l];
    }
}

// ---------------- final column mean ----------------
__global__ void zero_out_kernel(float* __restrict__ out) { out[threadIdx.x] = 0.0f; }

__global__ void colmean_kernel(const float* __restrict__ xc, float* __restrict__ out, int N) {
    int t = threadIdx.x;  // 128
    float s = 0.0f;
    for (int r = blockIdx.x; r < N; r += gridDim.x) s += xc[(size_t)r * HID + t];
    atomicAdd(&out[t], s * (1.0f / N));
}

// ---------------- host orchestration ----------------
static inline int ceil_div(int a, int b) { return (a + b - 1) / b; }

extern "C" void kernel_launch(void* const* d_in, const int* in_sizes, int n_in,
                              void* d_out, int out_size) {
    const float* x_node       = (const float*)d_in[0];
    const float* x_class      = (const float*)d_in[1];
    const int*   member_src   = (const int*)d_in[2];
    const int*   member_dst   = (const int*)d_in[3];
    const int*   contains_src = (const int*)d_in[4];
    const int*   contains_dst = (const int*)d_in[5];
    const float* npw = (const float*)d_in[6];
    const float* npb = (const float*)d_in[7];
    const float* cpw = (const float*)d_in[8];
    const float* cpb = (const float*)d_in[9];
    const float* n2c_wl   = (const float*)d_in[10];
    const float* n2c_bl   = (const float*)d_in[11];
    const float* n2c_wr   = (const float*)d_in[12];
    const float* n2c_br   = (const float*)d_in[13];
    const float* n2c_att  = (const float*)d_in[14];
    const float* n2c_bias = (const float*)d_in[15];
    const float* c2n_wl   = (const float*)d_in[16];
    const float* c2n_bl   = (const float*)d_in[17];
    const float* c2n_wr   = (const float*)d_in[18];
    const float* c2n_br   = (const float*)d_in[19];
    const float* c2n_att  = (const float*)d_in[20];
    const float* c2n_bias = (const float*)d_in[21];
    const float* ln_cg = (const float*)d_in[22];
    const float* ln_cb = (const float*)d_in[23];
    const float* ln_ng = (const float*)d_in[24];
    const float* ln_nb = (const float*)d_in[25];
    float* out = (float*)d_out;

    int E = in_sizes[2];

    float *xn, *xc, *xl, *xr, *agg, *score, *smax, *den;
    cudaGetSymbolAddress((void**)&xn, g_xn);
    cudaGetSymbolAddress((void**)&xc, g_xc);
    cudaGetSymbolAddress((void**)&xl, g_xl);
    cudaGetSymbolAddress((void**)&xr, g_xr);
    cudaGetSymbolAddress((void**)&agg, g_agg);
    cudaGetSymbolAddress((void**)&score, g_score);
    cudaGetSymbolAddress((void**)&smax, g_smax);
    cudaGetSymbolAddress((void**)&den, g_den);

    const float NEG_INF = -INFINITY;

    // input projections
    proj_kernel<<<NN, 128>>>(x_node, npw, npb, xn, NN, ND);
    proj_kernel<<<NC, 128>>>(x_class, cpw, cpb, xc, NC, CD);

    for (int l = 0; l < NL; l++) {
        // ---- n2c: src = xn (NN), dst = xc (NC) ----
        gemm128_kernel<<<ceil_div(NN, 64), 256>>>(xn, n2c_wl + (size_t)l * HID * HID,
                                                  n2c_bl + l * HID, xl, NN);
        gemm128_kernel<<<ceil_div(NC, 64), 256>>>(xc, n2c_wr + (size_t)l * HID * HID,
                                                  n2c_br + l * HID, xr, NC);
        fill_kernel<<<ceil_div(NC * NH, 256), 256>>>(smax, NEG_INF, NC * NH);
        fill_kernel<<<ceil_div(NC * NH, 256), 256>>>(den, 0.0f, NC * NH);
        fill_kernel<<<ceil_div(NC * HID, 256), 256>>>(agg, 0.0f, NC * HID);
        epass1_kernel<<<ceil_div(E * 32, 256), 256>>>(member_src, member_dst, xl, xr,
                                                      n2c_att + l * HID, score, smax, E);
        epass2_kernel<<<ceil_div(E * NH, 256), 256>>>(member_dst, score, smax, den, E * NH);
        epass3_kernel<<<ceil_div(E * 32, 256), 256>>>(member_src, member_dst, xl, score,
                                                      den, agg, E);
        ln_kernel<<<ceil_div(NC * 32, 256), 256>>>(xc, agg, n2c_bias + l * HID,
                                                   ln_cg + l * HID, ln_cb + l * HID, NC);

        // ---- c2n: src = xc (NC), dst = xn (NN) ----
        gemm128_kernel<<<ceil_div(NC, 64), 256>>>(xc, c2n_wl + (size_t)l * HID * HID,
                                                  c2n_bl + l * HID, xl, NC);
        gemm128_kernel<<<ceil_div(NN, 64), 256>>>(xn, c2n_wr + (size_t)l * HID * HID,
                                                  c2n_br + l * HID, xr, NN);
        fill_kernel<<<ceil_div(NN * NH, 256), 256>>>(smax, NEG_INF, NN * NH);
        fill_kernel<<<ceil_div(NN * NH, 256), 256>>>(den, 0.0f, NN * NH);
        fill_kernel<<<ceil_div(NN * HID, 256), 256>>>(agg, 0.0f, NN * HID);
        epass1_kernel<<<ceil_div(E * 32, 256), 256>>>(contains_src, contains_dst, xl, xr,
                                                      c2n_att + l * HID, score, smax, E);
        epass2_kernel<<<ceil_div(E * NH, 256), 256>>>(contains_dst, score, smax, den, E * NH);
        epass3_kernel<<<ceil_div(E * 32, 256), 256>>>(contains_src, contains_dst, xl, score,
                                                      den, agg, E);
        ln_kernel<<<ceil_div(NN * 32, 256), 256>>>(xn, agg, c2n_bias + l * HID,
                                                   ln_ng + l * HID, ln_nb + l * HID, NN);
    }

    // final: out = mean over rows of xc
    zero_out_kernel<<<1, 128>>>(out);
    colmean_kernel<<<256, 128>>>(xc, out, NC);
}

// round 2
// speedup vs baseline: 1.3216x; 1.3216x over previous
#include <cuda_runtime.h>
#include <math.h>

// ---------------- problem constants ----------------
#define NN 100000
#define NC 50000
#define EE 400000
#define ND 43
#define CD 2
#define HID 128
#define NL 4
#define SLOPE 0.2f
#define LNEPS 1e-5f

// ---------------- device scratch (static, no allocation) ----------------
__device__ float g_xn[(size_t)NN * HID];
__device__ float g_xc[(size_t)NC * HID];
__device__ float g_xl[(size_t)NN * HID];
__device__ float g_xr[(size_t)NN * HID];
__device__ int g_deg[NN];
__device__ int g_cur[NN];
__device__ int g_off_m[NC + 1];   // CSR offsets, member edges (dst = class)
__device__ int g_off_c[NN + 1];   // CSR offsets, contains edges (dst = node)
__device__ int g_src_m[EE];       // permuted src for member
__device__ int g_src_c[EE];       // permuted src for contains

// ---------------- f32x2 helpers ----------------
__device__ __forceinline__ void ffma2(unsigned long long& d, unsigned long long a,
                                      unsigned long long b) {
    asm("fma.rn.f32x2 %0, %1, %2, %0;" : "+l"(d) : "l"(a), "l"(b));
}
__device__ __forceinline__ unsigned long long dup2(float x) {
    unsigned long long r;
    asm("mov.b64 %0, {%1, %1};" : "=l"(r) : "f"(x));
    return r;
}
__device__ __forceinline__ float2 unpk2(unsigned long long v) {
    float2 r;
    asm("mov.b64 {%0, %1}, %2;" : "=f"(r.x), "=f"(r.y) : "l"(v));
    return r;
}

// ---------------- CSR build ----------------
__global__ void zero_int_kernel(int* __restrict__ p, int n) {
    int i = blockIdx.x * blockDim.x + threadIdx.x;
    if (i < n) p[i] = 0;
}
__global__ void hist_kernel(const int* __restrict__ dst, int* __restrict__ deg, int E) {
    int i = blockIdx.x * blockDim.x + threadIdx.x;
    if (i < E) atomicAdd(&deg[dst[i]], 1);
}
// single-block exclusive scan; also writes cursor copy and total at off[n]
__global__ void scan_kernel(const int* __restrict__ deg, int* __restrict__ off,
                            int* __restrict__ cur, int n) {
    __shared__ int part[1024];
    int t = threadIdx.x;
    int chunk = (n + 1023) >> 10;
    int s0 = t * chunk;
    int s1 = s0 + chunk;
    if (s1 > n) s1 = n;
    if (s0 > n) s0 = n;
    int sum = 0;
    for (int i = s0; i < s1; i++) sum += deg[i];
    part[t] = sum;
    __syncthreads();
    for (int d = 1; d < 1024; d <<= 1) {
        int v = (t >= d) ? part[t - d] : 0;
        __syncthreads();
        part[t] += v;
        __syncthreads();
    }
    int run = (t > 0) ? part[t - 1] : 0;
    for (int i = s0; i < s1; i++) {
        off[i] = run;
        cur[i] = run;
        run += deg[i];
    }
    if (t == 1023) off[n] = part[1023];
}
__global__ void scatter_kernel(const int* __restrict__ src, const int* __restrict__ dst,
                               int* __restrict__ cur, int* __restrict__ csrc, int E) {
    int i = blockIdx.x * blockDim.x + threadIdx.x;
    if (i < E) {
        int p = atomicAdd(&cur[dst[i]], 1);
        csrc[p] = src[i];
    }
}

// ---------------- small-K projection: Y[N,128] = X[N,K] @ W[K,128] + b ----------------
__global__ void proj_kernel(const float* __restrict__ X, const float* __restrict__ W,
                            const float* __restrict__ b, float* __restrict__ Y,
                            int N, int K) {
    __shared__ float xs[64];
    int row = blockIdx.x;
    if (row >= N) return;
    int n = threadIdx.x;  // 128 threads
    if (n < K) xs[n] = X[(size_t)row * K + n];
    __syncthreads();
    float acc = b[n];
    for (int k = 0; k < K; k++) acc = fmaf(xs[k], W[k * HID + n], acc);
    Y[(size_t)row * HID + n] = acc;
}

// ---------------- SGEMM: Y[N,128] = X[N,128] @ W[128,128] + b (f32x2 packed) ------------
// 256 threads, tile 128x128, BK=8, double-buffered smem, 8x8 microtile (rows paired)
__global__ __launch_bounds__(256, 2)
void sgemm128(const float* __restrict__ X, const float* __restrict__ W,
              const float* __restrict__ bias, float* __restrict__ Y, int N) {
    __shared__ __align__(16) float As[2][8][128];  // As[buf][k][m]
    __shared__ __align__(16) float Bs[2][8][128];  // Bs[buf][k][n]
    int tid = threadIdx.x;
    int rowBase = blockIdx.x * 128;
    int lr = tid >> 1;            // 0..127 tile row (A load)
    int lk = (tid & 1) * 4;       // 0/4 k offset (A load)
    int wk = tid >> 5;            // 0..7 (B load)
    int wn = (tid & 31) * 4;      // 0..124 (B load)
    int tx = tid & 15;            // col group
    int ty = tid >> 4;            // row group
    int arow = rowBase + lr;
    bool aok = arow < N;
    const float4 z4 = make_float4(0.f, 0.f, 0.f, 0.f);

    unsigned long long acc[4][8];
#pragma unroll
    for (int i = 0; i < 4; i++)
#pragma unroll
        for (int j = 0; j < 8; j++) acc[i][j] = 0ull;

    // prologue: stage 0
    float4 xv = aok ? *(const float4*)(X + (size_t)arow * HID + lk) : z4;
    float4 wv = *(const float4*)(W + (size_t)wk * HID + wn);
    As[0][lk + 0][lr] = xv.x; As[0][lk + 1][lr] = xv.y;
    As[0][lk + 2][lr] = xv.z; As[0][lk + 3][lr] = xv.w;
    *(float4*)&Bs[0][wk][wn] = wv;
    __syncthreads();

    int buf = 0;
#pragma unroll 1
    for (int t = 0; t < 16; t++) {
        if (t < 15) {
            int k0 = (t + 1) * 8;
            xv = aok ? *(const float4*)(X + (size_t)arow * HID + k0 + lk) : z4;
            wv = *(const float4*)(W + (size_t)(k0 + wk) * HID + wn);
        }
#pragma unroll
        for (int k = 0; k < 8; k++) {
            ulonglong2 a01 = *(const ulonglong2*)&As[buf][k][ty * 8];
            ulonglong2 a23 = *(const ulonglong2*)&As[buf][k][ty * 8 + 4];
            float4 b0 = *(const float4*)&Bs[buf][k][tx * 8];
            float4 b1 = *(const float4*)&Bs[buf][k][tx * 8 + 4];
            unsigned long long av[4] = {a01.x, a01.y, a23.x, a23.y};
            unsigned long long bd[8] = {dup2(b0.x), dup2(b0.y), dup2(b0.z), dup2(b0.w),
                                        dup2(b1.x), dup2(b1.y), dup2(b1.z), dup2(b1.w)};
#pragma unroll
            for (int i = 0; i < 4; i++)
#pragma unroll
                for (int j = 0; j < 8; j++) ffma2(acc[i][j], av[i], bd[j]);
        }
        if (t < 15) {
            int nb = buf ^ 1;
            As[nb][lk + 0][lr] = xv.x; As[nb][lk + 1][lr] = xv.y;
            As[nb][lk + 2][lr] = xv.z; As[nb][lk + 3][lr] = xv.w;
            *(float4*)&Bs[nb][wk][wn] = wv;
            __syncthreads();
            buf = nb;
        }
    }

    // epilogue
    float bcol[8];
#pragma unroll
    for (int j = 0; j < 8; j++) bcol[j] = bias[tx * 8 + j];
#pragma unroll
    for (int i = 0; i < 4; i++) {
        float o0[8], o1[8];
#pragma unroll
        for (int j = 0; j < 8; j++) {
            float2 p = unpk2(acc[i][j]);
            o0[j] = p.x + bcol[j];
            o1[j] = p.y + bcol[j];
        }
        int row0 = rowBase + ty * 8 + i * 2;
        if (row0 < N) {
            float* yp = Y + (size_t)row0 * HID + tx * 8;
            *(float4*)yp = make_float4(o0[0], o0[1], o0[2], o0[3]);
            *(float4*)(yp + 4) = make_float4(o0[4], o0[5], o0[6], o0[7]);
        }
        if (row0 + 1 < N) {
            float* yp = Y + (size_t)(row0 + 1) * HID + tx * 8;
            *(float4*)yp = make_float4(o1[0], o1[1], o1[2], o1[3]);
            *(float4*)(yp + 4) = make_float4(o1[4], o1[5], o1[6], o1[7]);
        }
    }
}

// ---------------- fused GATv2 aggregate + bias + residual + LayerNorm ----------------
// one warp per dst node; lane l owns channels [4l, 4l+3] (head = l>>3);
// online softmax over incoming edges via CSR — no atomics, single gather per edge.
__global__ void gat_kernel(const int* __restrict__ off, const int* __restrict__ csrc,
                           const float* __restrict__ xl, const float* __restrict__ xr,
                           const float* __restrict__ att, const float* __restrict__ bias,
                           const float* __restrict__ lng, const float* __restrict__ lnb,
                           float* __restrict__ x, int n_dst) {
    int d = (blockIdx.x * blockDim.x + threadIdx.x) >> 5;
    if (d >= n_dst) return;
    int l = threadIdx.x & 31;
    int ofs = l * 4;

    float4 xr4 = *(const float4*)(xr + (size_t)d * HID + ofs);
    float4 at4 = *(const float4*)(att + ofs);
    int e0 = off[d], e1 = off[d + 1];

    float m = -INFINITY, den = 0.f;
    float4 acc = make_float4(0.f, 0.f, 0.f, 0.f);

    int snext = (e0 < e1) ? csrc[e0] : 0;
    for (int e = e0; e < e1; e++) {
        int s = snext;
        if (e + 1 < e1) snext = csrc[e + 1];
        float4 xl4 = *(const float4*)(xl + (size_t)s * HID + ofs);
        float vx = xl4.x + xr4.x; vx = vx > 0.f ? vx : SLOPE * vx;
        float vy = xl4.y + xr4.y; vy = vy > 0.f ? vy : SLOPE * vy;
        float vz = xl4.z + xr4.z; vz = vz > 0.f ? vz : SLOPE * vz;
        float vw = xl4.w + xr4.w; vw = vw > 0.f ? vw : SLOPE * vw;
        float sc = vx * at4.x + vy * at4.y + vz * at4.z + vw * at4.w;
        sc += __shfl_xor_sync(0xffffffffu, sc, 1);
        sc += __shfl_xor_sync(0xffffffffu, sc, 2);
        sc += __shfl_xor_sync(0xffffffffu, sc, 4);
        float nm = fmaxf(m, sc);
        float f = __expf(m - nm);
        float ee = __expf(sc - nm);
        den = den * f + ee;
        acc.x = acc.x * f + ee * xl4.x;
        acc.y = acc.y * f + ee * xl4.y;
        acc.z = acc.z * f + ee * xl4.z;
        acc.w = acc.w * f + ee * xl4.w;
        m = nm;
    }

    float inv = (e1 > e0) ? 1.0f / den : 0.0f;
    float4 b4 = *(const float4*)(bias + ofs);
    float4 x4 = *(const float4*)(x + (size_t)d * HID + ofs);
    float4 o;
    o.x = acc.x * inv + b4.x + x4.x;
    o.y = acc.y * inv + b4.y + x4.y;
    o.z = acc.z * inv + b4.z + x4.z;
    o.w = acc.w * inv + b4.w + x4.w;

    float s = o.x + o.y + o.z + o.w;
#pragma unroll
    for (int k = 16; k > 0; k >>= 1) s += __shfl_xor_sync(0xffffffffu, s, k);
    float mu = s * (1.0f / HID);
    float q = (o.x - mu) * (o.x - mu) + (o.y - mu) * (o.y - mu) +
              (o.z - mu) * (o.z - mu) + (o.w - mu) * (o.w - mu);
#pragma unroll
    for (int k = 16; k > 0; k >>= 1) q += __shfl_xor_sync(0xffffffffu, q, k);
    float rs = rsqrtf(q * (1.0f / HID) + LNEPS);
    float4 g4 = *(const float4*)(lng + ofs);
    float4 bb4 = *(const float4*)(lnb + ofs);
    o.x = (o.x - mu) * rs * g4.x + bb4.x;
    o.y = (o.y - mu) * rs * g4.y + bb4.y;
    o.z = (o.z - mu) * rs * g4.z + bb4.z;
    o.w = (o.w - mu) * rs * g4.w + bb4.w;
    *(float4*)(x + (size_t)d * HID + ofs) = o;
}

// ---------------- final column mean ----------------
__global__ void zero_out_kernel(float* __restrict__ out) { out[threadIdx.x] = 0.0f; }

__global__ void colmean_kernel(const float* __restrict__ xc, float* __restrict__ out, int N) {
    int t = threadIdx.x;  // 128
    float s = 0.0f;
    for (int r = blockIdx.x; r < N; r += gridDim.x) s += xc[(size_t)r * HID + t];
    atomicAdd(&out[t], s * (1.0f / N));
}

// ---------------- host orchestration ----------------
static inline int ceil_div(int a, int b) { return (a + b - 1) / b; }

extern "C" void kernel_launch(void* const* d_in, const int* in_sizes, int n_in,
                              void* d_out, int out_size) {
    const float* x_node       = (const float*)d_in[0];
    const float* x_class      = (const float*)d_in[1];
    const int*   member_src   = (const int*)d_in[2];
    const int*   member_dst   = (const int*)d_in[3];
    const int*   contains_src = (const int*)d_in[4];
    const int*   contains_dst = (const int*)d_in[5];
    const float* npw = (const float*)d_in[6];
    const float* npb = (const float*)d_in[7];
    const float* cpw = (const float*)d_in[8];
    const float* cpb = (const float*)d_in[9];
    const float* n2c_wl   = (const float*)d_in[10];
    const float* n2c_bl   = (const float*)d_in[11];
    const float* n2c_wr   = (const float*)d_in[12];
    const float* n2c_br   = (const float*)d_in[13];
    const float* n2c_att  = (const float*)d_in[14];
    const float* n2c_bias = (const float*)d_in[15];
    const float* c2n_wl   = (const float*)d_in[16];
    const float* c2n_bl   = (const float*)d_in[17];
    const float* c2n_wr   = (const float*)d_in[18];
    const float* c2n_br   = (const float*)d_in[19];
    const float* c2n_att  = (const float*)d_in[20];
    const float* c2n_bias = (const float*)d_in[21];
    const float* ln_cg = (const float*)d_in[22];
    const float* ln_cb = (const float*)d_in[23];
    const float* ln_ng = (const float*)d_in[24];
    const float* ln_nb = (const float*)d_in[25];
    float* out = (float*)d_out;

    int E = in_sizes[2];

    float *xn, *xc, *xl, *xr;
    int *deg, *cur, *off_m, *off_c, *src_m, *src_c;
    cudaGetSymbolAddress((void**)&xn, g_xn);
    cudaGetSymbolAddress((void**)&xc, g_xc);
    cudaGetSymbolAddress((void**)&xl, g_xl);
    cudaGetSymbolAddress((void**)&xr, g_xr);
    cudaGetSymbolAddress((void**)&deg, g_deg);
    cudaGetSymbolAddress((void**)&cur, g_cur);
    cudaGetSymbolAddress((void**)&off_m, g_off_m);
    cudaGetSymbolAddress((void**)&off_c, g_off_c);
    cudaGetSymbolAddress((void**)&src_m, g_src_m);
    cudaGetSymbolAddress((void**)&src_c, g_src_c);

    int gE = ceil_div(E, 256);

    // ---- CSR build: member (dst in NC) ----
    zero_int_kernel<<<ceil_div(NC, 256), 256>>>(deg, NC);
    hist_kernel<<<gE, 256>>>(member_dst, deg, E);
    scan_kernel<<<1, 1024>>>(deg, off_m, cur, NC);
    scatter_kernel<<<gE, 256>>>(member_src, member_dst, cur, src_m, E);
    // ---- CSR build: contains (dst in NN) ----
    zero_int_kernel<<<ceil_div(NN, 256), 256>>>(deg, NN);
    hist_kernel<<<gE, 256>>>(contains_dst, deg, E);
    scan_kernel<<<1, 1024>>>(deg, off_c, cur, NN);
    scatter_kernel<<<gE, 256>>>(contains_src, contains_dst, cur, src_c, E);

    // ---- input projections ----
    proj_kernel<<<NN, 128>>>(x_node, npw, npb, xn, NN, ND);
    proj_kernel<<<NC, 128>>>(x_class, cpw, cpb, xc, NC, CD);

    for (int l = 0; l < NL; l++) {
        // ---- n2c: src = xn (NN), dst = xc (NC) ----
        sgemm128<<<ceil_div(NN, 128), 256>>>(xn, n2c_wl + (size_t)l * HID * HID,
                                             n2c_bl + l * HID, xl, NN);
        sgemm128<<<ceil_div(NC, 128), 256>>>(xc, n2c_wr + (size_t)l * HID * HID,
                                             n2c_br + l * HID, xr, NC);
        gat_kernel<<<ceil_div(NC * 32, 256), 256>>>(off_m, src_m, xl, xr,
                                                    n2c_att + l * HID, n2c_bias + l * HID,
                                                    ln_cg + l * HID, ln_cb + l * HID,
                                                    xc, NC);
        // ---- c2n: src = xc (NC), dst = xn (NN) ----
        sgemm128<<<ceil_div(NC, 128), 256>>>(xc, c2n_wl + (size_t)l * HID * HID,
                                             c2n_bl + l * HID, xl, NC);
        sgemm128<<<ceil_div(NN, 128), 256>>>(xn, c2n_wr + (size_t)l * HID * HID,
                                             c2n_br + l * HID, xr, NN);
        gat_kernel<<<ceil_div(NN * 32, 256), 256>>>(off_c, src_c, xl, xr,
                                                    c2n_att + l * HID, c2n_bias + l * HID,
                                                    ln_ng + l * HID, ln_nb + l * HID,
                                                    xn, NN);
    }

    // final: out = mean over rows of xc
    zero_out_kernel<<<1, 128>>>(out);
    colmean_kernel<<<256, 128>>>(xc, out, NC);
}

// round 3
// speedup vs baseline: 1.4923x; 1.1292x over previous
#include <cuda_runtime.h>
#include <math.h>

// ---------------- problem constants ----------------
#define NN 100000
#define NC 50000
#define EE 400000
#define ND 43
#define CD 2
#define HID 128
#define NL 4
#define SLOPE 0.2f
#define LNEPS 1e-5f

// ---------------- device scratch (static, no allocation) ----------------
__device__ float g_xn[(size_t)NN * HID];
__device__ float g_xc[(size_t)NC * HID];
__device__ float g_xl[(size_t)NN * HID];
__device__ float g_xr[(size_t)NN * HID];
__device__ int g_deg_m[NC];
__device__ int g_cur_m[NC];
__device__ int g_deg_c[NN];
__device__ int g_cur_c[NN];
__device__ int g_off_m[NC + 1];   // CSR offsets, member edges (dst = class)
__device__ int g_off_c[NN + 1];   // CSR offsets, contains edges (dst = node)
__device__ int g_src_m[EE];       // permuted src for member
__device__ int g_src_c[EE];       // permuted src for contains

// ---------------- f32x2 helpers ----------------
__device__ __forceinline__ void ffma2(unsigned long long& d, unsigned long long a,
                                      unsigned long long b) {
    asm("fma.rn.f32x2 %0, %1, %2, %0;" : "+l"(d) : "l"(a), "l"(b));
}
__device__ __forceinline__ unsigned long long dup2(float x) {
    unsigned long long r;
    asm("mov.b64 %0, {%1, %1};" : "=l"(r) : "f"(x));
    return r;
}
__device__ __forceinline__ float2 unpk2(unsigned long long v) {
    float2 r;
    asm("mov.b64 {%0, %1}, %2;" : "=f"(r.x), "=f"(r.y) : "l"(v));
    return r;
}

// ---------------- merged input projection ----------------
// blocks [0, NN): node rows (K=ND); blocks [NN, NN+NC): class rows (K=CD)
__global__ void proj_both_kernel(const float* __restrict__ Xn, const float* __restrict__ Wn,
                                 const float* __restrict__ bn, float* __restrict__ Yn,
                                 const float* __restrict__ Xc, const float* __restrict__ Wc,
                                 const float* __restrict__ bc, float* __restrict__ Yc) {
    __shared__ float xs[64];
    int blk = blockIdx.x;
    int n = threadIdx.x;  // 128 threads
    const float* X;
    const float* W;
    const float* b;
    float* Y;
    int row, K;
    if (blk < NN) {
        X = Xn; W = Wn; b = bn; Y = Yn; row = blk; K = ND;
    } else {
        X = Xc; W = Wc; b = bc; Y = Yc; row = blk - NN; K = CD;
    }
    if (n < K) xs[n] = X[(size_t)row * K + n];
    __syncthreads();
    float acc = b[n];
    for (int k = 0; k < K; k++) acc = fmaf(xs[k], W[k * HID + n], acc);
    Y[(size_t)row * HID + n] = acc;
}

// ---------------- CSR build (both graphs per kernel) ----------------
__global__ void build_zero_kernel(int* __restrict__ dm, int* __restrict__ dc) {
    int i = blockIdx.x * blockDim.x + threadIdx.x;
    if (i < NC) dm[i] = 0;
    if (i < NN) dc[i] = 0;
}
__global__ void build_hist_kernel(const int* __restrict__ mdst, const int* __restrict__ cdst,
                                  int* __restrict__ dm, int* __restrict__ dc, int E) {
    int i = blockIdx.x * blockDim.x + threadIdx.x;
    if (i < E)
        atomicAdd(&dm[mdst[i]], 1);
    else if (i < 2 * E)
        atomicAdd(&dc[cdst[i - E]], 1);
}
// gridDim=2; block 0 scans member, block 1 scans contains
__global__ void build_scan_kernel(const int* __restrict__ dm, int* __restrict__ om,
                                  int* __restrict__ cm,
                                  const int* __restrict__ dc, int* __restrict__ oc,
                                  int* __restrict__ cc) {
    __shared__ int part[1024];
    const int* deg;
    int *off, *cur, n;
    if (blockIdx.x == 0) { deg = dm; off = om; cur = cm; n = NC; }
    else                 { deg = dc; off = oc; cur = cc; n = NN; }
    int t = threadIdx.x;
    int chunk = (n + 1023) >> 10;
    int s0 = t * chunk;
    int s1 = s0 + chunk;
    if (s1 > n) s1 = n;
    if (s0 > n) s0 = n;
    int sum = 0;
    for (int i = s0; i < s1; i++) sum += deg[i];
    part[t] = sum;
    __syncthreads();
    for (int d = 1; d < 1024; d <<= 1) {
        int v = (t >= d) ? part[t - d] : 0;
        __syncthreads();
        part[t] += v;
        __syncthreads();
    }
    int run = (t > 0) ? part[t - 1] : 0;
    for (int i = s0; i < s1; i++) {
        off[i] = run;
        cur[i] = run;
        run += deg[i];
    }
    if (t == 1023) off[n] = part[1023];
}
__global__ void build_scatter_kernel(const int* __restrict__ msrc, const int* __restrict__ mdst,
                                     const int* __restrict__ csrc_e, const int* __restrict__ cdst,
                                     int* __restrict__ cm, int* __restrict__ cc,
                                     int* __restrict__ sm, int* __restrict__ sc, int E) {
    int i = blockIdx.x * blockDim.x + threadIdx.x;
    if (i < E) {
        int p = atomicAdd(&cm[mdst[i]], 1);
        sm[p] = msrc[i];
    } else if (i < 2 * E) {
        int j = i - E;
        int p = atomicAdd(&cc[cdst[j]], 1);
        sc[p] = csrc_e[j];
    }
}

// ---------------- dual SGEMM: two GEMMs (Y = X @ W + b, HIDxHID weights) in one grid ----
// 256 threads, tile 128x128, BK=8, double-buffered smem, 8x8 microtile, f32x2 packed
__global__ __launch_bounds__(256, 2)
void sgemm128_dual(const float* __restrict__ X1, const float* __restrict__ W1,
                   const float* __restrict__ b1, float* __restrict__ Y1, int N1, int g1,
                   const float* __restrict__ X2, const float* __restrict__ W2,
                   const float* __restrict__ b2, float* __restrict__ Y2, int N2) {
    __shared__ __align__(16) float As[2][8][128];  // As[buf][k][m]
    __shared__ __align__(16) float Bs[2][8][128];  // Bs[buf][k][n]
    const float* X;
    const float* W;
    const float* bias;
    float* Y;
    int N, rowBase;
    if (blockIdx.x < (unsigned)g1) {
        X = X1; W = W1; bias = b1; Y = Y1; N = N1; rowBase = blockIdx.x * 128;
    } else {
        X = X2; W = W2; bias = b2; Y = Y2; N = N2; rowBase = (blockIdx.x - g1) * 128;
    }
    int tid = threadIdx.x;
    int lr = tid >> 1;            // 0..127 tile row (A load)
    int lk = (tid & 1) * 4;       // 0/4 k offset (A load)
    int wk = tid >> 5;            // 0..7 (B load)
    int wn = (tid & 31) * 4;      // 0..124 (B load)
    int tx = tid & 15;            // col group
    int ty = tid >> 4;            // row group
    int arow = rowBase + lr;
    bool aok = arow < N;
    const float4 z4 = make_float4(0.f, 0.f, 0.f, 0.f);

    unsigned long long acc[4][8];
#pragma unroll
    for (int i = 0; i < 4; i++)
#pragma unroll
        for (int j = 0; j < 8; j++) acc[i][j] = 0ull;

    // prologue: stage 0
    float4 xv = aok ? *(const float4*)(X + (size_t)arow * HID + lk) : z4;
    float4 wv = *(const float4*)(W + (size_t)wk * HID + wn);
    As[0][lk + 0][lr] = xv.x; As[0][lk + 1][lr] = xv.y;
    As[0][lk + 2][lr] = xv.z; As[0][lk + 3][lr] = xv.w;
    *(float4*)&Bs[0][wk][wn] = wv;
    __syncthreads();

    int buf = 0;
#pragma unroll 1
    for (int t = 0; t < 16; t++) {
        if (t < 15) {
            int k0 = (t + 1) * 8;
            xv = aok ? *(const float4*)(X + (size_t)arow * HID + k0 + lk) : z4;
            wv = *(const float4*)(W + (size_t)(k0 + wk) * HID + wn);
        }
#pragma unroll
        for (int k = 0; k < 8; k++) {
            ulonglong2 a01 = *(const ulonglong2*)&As[buf][k][ty * 8];
            ulonglong2 a23 = *(const ulonglong2*)&As[buf][k][ty * 8 + 4];
            float4 b0 = *(const float4*)&Bs[buf][k][tx * 8];
            float4 b1 = *(const float4*)&Bs[buf][k][tx * 8 + 4];
            unsigned long long av[4] = {a01.x, a01.y, a23.x, a23.y};
            unsigned long long bd[8] = {dup2(b0.x), dup2(b0.y), dup2(b0.z), dup2(b0.w),
                                        dup2(b1.x), dup2(b1.y), dup2(b1.z), dup2(b1.w)};
#pragma unroll
            for (int i = 0; i < 4; i++)
#pragma unroll
                for (int j = 0; j < 8; j++) ffma2(acc[i][j], av[i], bd[j]);
        }
        if (t < 15) {
            int nb = buf ^ 1;
            As[nb][lk + 0][lr] = xv.x; As[nb][lk + 1][lr] = xv.y;
            As[nb][lk + 2][lr] = xv.z; As[nb][lk + 3][lr] = xv.w;
            *(float4*)&Bs[nb][wk][wn] = wv;
            __syncthreads();
            buf = nb;
        }
    }

    // epilogue
    float bcol[8];
#pragma unroll
    for (int j = 0; j < 8; j++) bcol[j] = bias[tx * 8 + j];
#pragma unroll
    for (int i = 0; i < 4; i++) {
        float o0[8], o1[8];
#pragma unroll
        for (int j = 0; j < 8; j++) {
            float2 p = unpk2(acc[i][j]);
            o0[j] = p.x + bcol[j];
            o1[j] = p.y + bcol[j];
        }
        int row0 = rowBase + ty * 8 + i * 2;
        if (row0 < N) {
            float* yp = Y + (size_t)row0 * HID + tx * 8;
            *(float4*)yp = make_float4(o0[0], o0[1], o0[2], o0[3]);
            *(float4*)(yp + 4) = make_float4(o0[4], o0[5], o0[6], o0[7]);
        }
        if (row0 + 1 < N) {
            float* yp = Y + (size_t)(row0 + 1) * HID + tx * 8;
            *(float4*)yp = make_float4(o1[0], o1[1], o1[2], o1[3]);
            *(float4*)(yp + 4) = make_float4(o1[4], o1[5], o1[6], o1[7]);
        }
    }
}

// ---------------- fused GATv2: two-pass softmax + bias + residual + LayerNorm ----------
// one warp per dst node; lane l owns channels [4l,4l+3]; head = l>>3.
// Pass 1: max score (parallel, only fmax carried). Pass 2: exp-sum + weighted acc.
__device__ __forceinline__ float edge_score(float4 xl4, float4 xr4, float4 at4) {
    float vx = xl4.x + xr4.x; vx = vx > 0.f ? vx : SLOPE * vx;
    float vy = xl4.y + xr4.y; vy = vy > 0.f ? vy : SLOPE * vy;
    float vz = xl4.z + xr4.z; vz = vz > 0.f ? vz : SLOPE * vz;
    float vw = xl4.w + xr4.w; vw = vw > 0.f ? vw : SLOPE * vw;
    float sc = vx * at4.x + vy * at4.y + vz * at4.z + vw * at4.w;
    sc += __shfl_xor_sync(0xffffffffu, sc, 1);
    sc += __shfl_xor_sync(0xffffffffu, sc, 2);
    sc += __shfl_xor_sync(0xffffffffu, sc, 4);
    return sc;  // per-head score, uniform within each 8-lane group
}

__global__ void gat_kernel(const int* __restrict__ off, const int* __restrict__ csrc,
                           const float* __restrict__ xl, const float* __restrict__ xr,
                           const float* __restrict__ att, const float* __restrict__ bias,
                           const float* __restrict__ lng, const float* __restrict__ lnb,
                           float* __restrict__ x, int n_dst) {
    int d = (blockIdx.x * blockDim.x + threadIdx.x) >> 5;
    if (d >= n_dst) return;
    int l = threadIdx.x & 31;
    int ofs = l * 4;

    float4 xr4 = *(const float4*)(xr + (size_t)d * HID + ofs);
    float4 at4 = *(const float4*)(att + ofs);
    int e0 = off[d], e1 = off[d + 1];

    // ---- pass 1: per-head max score ----
    float m = -1e30f;
    for (int e = e0; e < e1; e += 2) {
        int s0 = csrc[e];
        bool two = (e + 1 < e1);
        int s1 = two ? csrc[e + 1] : s0;
        float4 a = *(const float4*)(xl + (size_t)s0 * HID + ofs);
        float4 b = *(const float4*)(xl + (size_t)s1 * HID + ofs);
        float sa = edge_score(a, xr4, at4);
        float sb = edge_score(b, xr4, at4);
        m = fmaxf(m, two ? fmaxf(sa, sb) : sa);
    }

    // ---- pass 2: exp-sum + weighted accumulation ----
    float den = 0.f;
    float4 acc = make_float4(0.f, 0.f, 0.f, 0.f);
    for (int e = e0; e < e1; e += 2) {
        int s0 = csrc[e];
        bool two = (e + 1 < e1);
        int s1 = two ? csrc[e + 1] : s0;
        float4 a = *(const float4*)(xl + (size_t)s0 * HID + ofs);
        float4 b = *(const float4*)(xl + (size_t)s1 * HID + ofs);
        float sa = edge_score(a, xr4, at4);
        float sb = edge_score(b, xr4, at4);
        float ea = __expf(sa - m);
        float eb = two ? __expf(sb - m) : 0.f;
        den += ea + eb;
        acc.x = fmaf(ea, a.x, fmaf(eb, b.x, acc.x));
        acc.y = fmaf(ea, a.y, fmaf(eb, b.y, acc.y));
        acc.z = fmaf(ea, a.z, fmaf(eb, b.z, acc.z));
        acc.w = fmaf(ea, a.w, fmaf(eb, b.w, acc.w));
    }

    float inv = (e1 > e0) ? 1.0f / den : 0.0f;
    float4 b4 = *(const float4*)(bias + ofs);
    float4 x4 = *(const float4*)(x + (size_t)d * HID + ofs);
    float4 o;
    o.x = acc.x * inv + b4.x + x4.x;
    o.y = acc.y * inv + b4.y + x4.y;
    o.z = acc.z * inv + b4.z + x4.z;
    o.w = acc.w * inv + b4.w + x4.w;

    float s = o.x + o.y + o.z + o.w;
#pragma unroll
    for (int k = 16; k > 0; k >>= 1) s += __shfl_xor_sync(0xffffffffu, s, k);
    float mu = s * (1.0f / HID);
    float q = (o.x - mu) * (o.x - mu) + (o.y - mu) * (o.y - mu) +
              (o.z - mu) * (o.z - mu) + (o.w - mu) * (o.w - mu);
#pragma unroll
    for (int k = 16; k > 0; k >>= 1) q += __shfl_xor_sync(0xffffffffu, q, k);
    float rs = rsqrtf(q * (1.0f / HID) + LNEPS);
    float4 g4 = *(const float4*)(lng + ofs);
    float4 bb4 = *(const float4*)(lnb + ofs);
    o.x = (o.x - mu) * rs * g4.x + bb4.x;
    o.y = (o.y - mu) * rs * g4.y + bb4.y;
    o.z = (o.z - mu) * rs * g4.z + bb4.z;
    o.w = (o.w - mu) * rs * g4.w + bb4.w;
    *(float4*)(x + (size_t)d * HID + ofs) = o;
}

// ---------------- final column mean ----------------
__global__ void zero_out_kernel(float* __restrict__ out) { out[threadIdx.x] = 0.0f; }

__global__ void colmean_kernel(const float* __restrict__ xc, float* __restrict__ out, int N) {
    int t = threadIdx.x;  // 128
    float s = 0.0f;
    for (int r = blockIdx.x; r < N; r += gridDim.x) s += xc[(size_t)r * HID + t];
    atomicAdd(&out[t], s * (1.0f / N));
}

// ---------------- host orchestration ----------------
static inline int ceil_div(int a, int b) { return (a + b - 1) / b; }

extern "C" void kernel_launch(void* const* d_in, const int* in_sizes, int n_in,
                              void* d_out, int out_size) {
    const float* x_node       = (const float*)d_in[0];
    const float* x_class      = (const float*)d_in[1];
    const int*   member_src   = (const int*)d_in[2];
    const int*   member_dst   = (const int*)d_in[3];
    const int*   contains_src = (const int*)d_in[4];
    const int*   contains_dst = (const int*)d_in[5];
    const float* npw = (const float*)d_in[6];
    const float* npb = (const float*)d_in[7];
    const float* cpw = (const float*)d_in[8];
    const float* cpb = (const float*)d_in[9];
    const float* n2c_wl   = (const float*)d_in[10];
    const float* n2c_bl   = (const float*)d_in[11];
    const float* n2c_wr   = (const float*)d_in[12];
    const float* n2c_br   = (const float*)d_in[13];
    const float* n2c_att  = (const float*)d_in[14];
    const float* n2c_bias = (const float*)d_in[15];
    const float* c2n_wl   = (const float*)d_in[16];
    const float* c2n_bl   = (const float*)d_in[17];
    const float* c2n_wr   = (const float*)d_in[18];
    const float* c2n_br   = (const float*)d_in[19];
    const float* c2n_att  = (const float*)d_in[20];
    const float* c2n_bias = (const float*)d_in[21];
    const float* ln_cg = (const float*)d_in[22];
    const float* ln_cb = (const float*)d_in[23];
    const float* ln_ng = (const float*)d_in[24];
    const float* ln_nb = (const float*)d_in[25];
    float* out = (float*)d_out;

    int E = in_sizes[2];

    float *xn, *xc, *xl, *xr;
    int *deg_m, *cur_m, *deg_c, *cur_c, *off_m, *off_c, *src_m, *src_c;
    cudaGetSymbolAddress((void**)&xn, g_xn);
    cudaGetSymbolAddress((void**)&xc, g_xc);
    cudaGetSymbolAddress((void**)&xl, g_xl);
    cudaGetSymbolAddress((void**)&xr, g_xr);
    cudaGetSymbolAddress((void**)&deg_m, g_deg_m);
    cudaGetSymbolAddress((void**)&cur_m, g_cur_m);
    cudaGetSymbolAddress((void**)&deg_c, g_deg_c);
    cudaGetSymbolAddress((void**)&cur_c, g_cur_c);
    cudaGetSymbolAddress((void**)&off_m, g_off_m);
    cudaGetSymbolAddress((void**)&off_c, g_off_c);
    cudaGetSymbolAddress((void**)&src_m, g_src_m);
    cudaGetSymbolAddress((void**)&src_c, g_src_c);

    int g2E = ceil_div(2 * E, 256);
    int gNNb = ceil_div(NN, 128);   // 782 blocks (NN gemm)
    int gNCb = ceil_div(NC, 128);   // 391 blocks (NC gemm)

    // launch 0: input projections (both)
    proj_both_kernel<<<NN + NC, 128>>>(x_node, npw, npb, xn, x_class, cpw, cpb, xc);
    // launches 1-4: CSR build (both graphs)
    build_zero_kernel<<<ceil_div(NN, 256), 256>>>(deg_m, deg_c);
    build_hist_kernel<<<g2E, 256>>>(member_dst, contains_dst, deg_m, deg_c, E);
    build_scan_kernel<<<2, 1024>>>(deg_m, off_m, cur_m, deg_c, off_c, cur_c);
    build_scatter_kernel<<<g2E, 256>>>(member_src, member_dst, contains_src, contains_dst,
                                       cur_m, cur_c, src_m, src_c, E);

    for (int l = 0; l < NL; l++) {
        // ---- n2c: xl = xn@wl [NN rows], xr = xc@wr [NC rows] ----
        sgemm128_dual<<<gNNb + gNCb, 256>>>(xn, n2c_wl + (size_t)l * HID * HID,
                                            n2c_bl + l * HID, xl, NN, gNNb,
                                            xc, n2c_wr + (size_t)l * HID * HID,
                                            n2c_br + l * HID, xr, NC);
        gat_kernel<<<ceil_div(NC * 32, 256), 256>>>(off_m, src_m, xl, xr,
                                                    n2c_att + l * HID, n2c_bias + l * HID,
                                                    ln_cg + l * HID, ln_cb + l * HID,
                                                    xc, NC);
        // ---- c2n: xl = xc@wl [NC rows], xr = xn@wr [NN rows] ----
        sgemm128_dual<<<gNCb + gNNb, 256>>>(xc, c2n_wl + (size_t)l * HID * HID,
                                            c2n_bl + l * HID, xl, NC, gNCb,
                                            xn, c2n_wr + (size_t)l * HID * HID,
                                            c2n_br + l * HID, xr, NN);
        gat_kernel<<<ceil_div(NN * 32, 256), 256>>>(off_c, src_c, xl, xr,
                                                    c2n_att + l * HID, c2n_bias + l * HID,
                                                    ln_ng + l * HID, ln_nb + l * HID,
                                                    xn, NN);
    }

    // final: out = mean over rows of xc
    zero_out_kernel<<<1, 128>>>(out);
    colmean_kernel<<<256, 128>>>(xc, out, NC);
}

// round 4
// speedup vs baseline: 1.6300x; 1.0923x over previous
#include <cuda_runtime.h>
#include <math.h>

// ---------------- problem constants ----------------
#define NN 100000
#define NC 50000
#define EE 400000
#define ND 43
#define CD 2
#define HID 128
#define NL 4
#define SLOPE 0.2f
#define LNEPS 1e-5f

#define SCHUNK 2048
#define NB_M ((NC + SCHUNK - 1) / SCHUNK)   // 25
#define NB_C ((NN + SCHUNK - 1) / SCHUNK)   // 49
#define NB_T (NB_M + NB_C)                  // 74

// ---------------- device scratch (static, no allocation) ----------------
__device__ float g_xn[(size_t)NN * HID];
__device__ float g_xc[(size_t)NC * HID];
__device__ float g_xl[(size_t)NN * HID];
__device__ float g_xr[(size_t)NN * HID];
__device__ int g_deg_m[NC];
__device__ int g_cur_m[NC];
__device__ int g_deg_c[NN];
__device__ int g_cur_c[NN];
__device__ int g_off_m[NC + 1];   // CSR offsets, member edges (dst = class)
__device__ int g_off_c[NN + 1];   // CSR offsets, contains edges (dst = node)
__device__ int g_src_m[EE];       // permuted src for member
__device__ int g_src_c[EE];       // permuted src for contains
__device__ int g_part[128];       // chunk partial sums / bases

// ---------------- f32x2 helpers ----------------
__device__ __forceinline__ void ffma2(unsigned long long& d, unsigned long long a,
                                      unsigned long long b) {
    asm("fma.rn.f32x2 %0, %1, %2, %0;" : "+l"(d) : "l"(a), "l"(b));
}
__device__ __forceinline__ unsigned long long dup2(float x) {
    unsigned long long r;
    asm("mov.b64 %0, {%1, %1};" : "=l"(r) : "f"(x));
    return r;
}
__device__ __forceinline__ float2 unpk2(unsigned long long v) {
    float2 r;
    asm("mov.b64 {%0, %1}, %2;" : "=f"(r.x), "=f"(r.y) : "l"(v));
    return r;
}

// ---------------- merged input projection ----------------
__global__ void proj_both_kernel(const float* __restrict__ Xn, const float* __restrict__ Wn,
                                 const float* __restrict__ bn, float* __restrict__ Yn,
                                 const float* __restrict__ Xc, const float* __restrict__ Wc,
                                 const float* __restrict__ bc, float* __restrict__ Yc) {
    __shared__ float xs[64];
    int blk = blockIdx.x;
    int n = threadIdx.x;  // 128 threads
    const float* X;
    const float* W;
    const float* b;
    float* Y;
    int row, K;
    if (blk < NN) {
        X = Xn; W = Wn; b = bn; Y = Yn; row = blk; K = ND;
    } else {
        X = Xc; W = Wc; b = bc; Y = Yc; row = blk - NN; K = CD;
    }
    if (n < K) xs[n] = X[(size_t)row * K + n];
    __syncthreads();
    float acc = b[n];
    for (int k = 0; k < K; k++) acc = fmaf(xs[k], W[k * HID + n], acc);
    Y[(size_t)row * HID + n] = acc;
}

// ---------------- CSR build ----------------
__global__ void build_zero_kernel(int* __restrict__ dm, int* __restrict__ dc) {
    int i = blockIdx.x * blockDim.x + threadIdx.x;
    if (i < NC) dm[i] = 0;
    if (i < NN) dc[i] = 0;
}
__global__ void build_hist_kernel(const int* __restrict__ mdst, const int* __restrict__ cdst,
                                  int* __restrict__ dm, int* __restrict__ dc, int E) {
    int i = blockIdx.x * blockDim.x + threadIdx.x;
    if (i < E)
        atomicAdd(&dm[mdst[i]], 1);
    else if (i < 2 * E)
        atomicAdd(&dc[cdst[i - E]], 1);
}
// phase A: per-chunk sums (grid = NB_T, 256 threads, 8 elems/thread)
__global__ void scanA_kernel(const int* __restrict__ dm, const int* __restrict__ dc,
                             int* __restrict__ part) {
    int b = blockIdx.x;
    const int* deg;
    int n, c0;
    if (b < NB_M) { deg = dm; n = NC; c0 = b * SCHUNK; }
    else          { deg = dc; n = NN; c0 = (b - NB_M) * SCHUNK; }
    int t = threadIdx.x;
    int base = c0 + t * 8;
    int s = 0;
#pragma unroll
    for (int i = 0; i < 8; i++) {
        int idx = base + i;
        if (idx < n) s += deg[idx];
    }
#pragma unroll
    for (int o = 16; o > 0; o >>= 1) s += __shfl_xor_sync(0xffffffffu, s, o);
    __shared__ int red[8];
    if ((t & 31) == 0) red[t >> 5] = s;
    __syncthreads();
    if (t == 0) {
        int tot = 0;
#pragma unroll
        for (int i = 0; i < 8; i++) tot += red[i];
        part[b] = tot;
    }
}
// phase B: segmented exclusive scan of 74 chunk sums (1 block)
__global__ void scanB_kernel(int* __restrict__ part, int* __restrict__ om,
                             int* __restrict__ oc, int E) {
    __shared__ int sm_[128];
    int t = threadIdx.x;  // 128
    sm_[t] = (t < NB_T) ? part[t] : 0;
    __syncthreads();
    if (t == 0) {
        int run = 0;
        for (int i = 0; i < NB_M; i++) { int x = sm_[i]; sm_[i] = run; run += x; }
        run = 0;
        for (int i = NB_M; i < NB_T; i++) { int x = sm_[i]; sm_[i] = run; run += x; }
        om[NC] = E;
        oc[NN] = E;
    }
    __syncthreads();
    if (t < NB_T) part[t] = sm_[t];
}
// phase C: chunk-local exclusive rescan + write off/cur
__global__ void scanC_kernel(const int* __restrict__ dm, const int* __restrict__ dc,
                             const int* __restrict__ part, int* __restrict__ om,
                             int* __restrict__ oc, int* __restrict__ cm,
                             int* __restrict__ cc) {
    int b = blockIdx.x;
    const int* deg;
    int *off, *cur;
    int n, c0;
    if (b < NB_M) { deg = dm; off = om; cur = cm; n = NC; c0 = b * SCHUNK; }
    else          { deg = dc; off = oc; cur = cc; n = NN; c0 = (b - NB_M) * SCHUNK; }
    int t = threadIdx.x;  // 256
    int base = c0 + t * 8;
    int v[8];
    int s = 0;
#pragma unroll
    for (int i = 0; i < 8; i++) {
        int idx = base + i;
        v[i] = (idx < n) ? deg[idx] : 0;
        s += v[i];
    }
    int lane = t & 31, w = t >> 5;
    int pre = s;
#pragma unroll
    for (int o = 1; o < 32; o <<= 1) {
        int u = __shfl_up_sync(0xffffffffu, pre, o);
        if (lane >= o) pre += u;
    }
    __shared__ int wsum[8];
    if (lane == 31) wsum[w] = pre;
    __syncthreads();
    if (t == 0) {
        int run = 0;
#pragma unroll
        for (int i = 0; i < 8; i++) { int x = wsum[i]; wsum[i] = run; run += x; }
    }
    __syncthreads();
    int ex = pre - s + wsum[w] + part[b];
#pragma unroll
    for (int i = 0; i < 8; i++) {
        int idx = base + i;
        if (idx < n) {
            off[idx] = ex;
            cur[idx] = ex;
            ex += v[i];
        }
    }
}
__global__ void build_scatter_kernel(const int* __restrict__ msrc, const int* __restrict__ mdst,
                                     const int* __restrict__ csrc_e, const int* __restrict__ cdst,
                                     int* __restrict__ cm, int* __restrict__ cc,
                                     int* __restrict__ sm, int* __restrict__ sc, int E) {
    int i = blockIdx.x * blockDim.x + threadIdx.x;
    if (i < E) {
        int p = atomicAdd(&cm[mdst[i]], 1);
        sm[p] = msrc[i];
    } else if (i < 2 * E) {
        int j = i - E;
        int p = atomicAdd(&cc[cdst[j]], 1);
        sc[p] = csrc_e[j];
    }
}

// ---------------- dual SGEMM (f32x2 packed) ----------------
__global__ __launch_bounds__(256, 2)
void sgemm128_dual(const float* __restrict__ X1, const float* __restrict__ W1,
                   const float* __restrict__ b1, float* __restrict__ Y1, int N1, int g1,
                   const float* __restrict__ X2, const float* __restrict__ W2,
                   const float* __restrict__ b2, float* __restrict__ Y2, int N2) {
    __shared__ __align__(16) float As[2][8][128];
    __shared__ __align__(16) float Bs[2][8][128];
    const float* X;
    const float* W;
    const float* bias;
    float* Y;
    int N, rowBase;
    if (blockIdx.x < (unsigned)g1) {
        X = X1; W = W1; bias = b1; Y = Y1; N = N1; rowBase = blockIdx.x * 128;
    } else {
        X = X2; W = W2; bias = b2; Y = Y2; N = N2; rowBase = (blockIdx.x - g1) * 128;
    }
    int tid = threadIdx.x;
    int lr = tid >> 1;
    int lk = (tid & 1) * 4;
    int wk = tid >> 5;
    int wn = (tid & 31) * 4;
    int tx = tid & 15;
    int ty = tid >> 4;
    int arow = rowBase + lr;
    bool aok = arow < N;
    const float4 z4 = make_float4(0.f, 0.f, 0.f, 0.f);

    unsigned long long acc[4][8];
#pragma unroll
    for (int i = 0; i < 4; i++)
#pragma unroll
        for (int j = 0; j < 8; j++) acc[i][j] = 0ull;

    float4 xv = aok ? *(const float4*)(X + (size_t)arow * HID + lk) : z4;
    float4 wv = *(const float4*)(W + (size_t)wk * HID + wn);
    As[0][lk + 0][lr] = xv.x; As[0][lk + 1][lr] = xv.y;
    As[0][lk + 2][lr] = xv.z; As[0][lk + 3][lr] = xv.w;
    *(float4*)&Bs[0][wk][wn] = wv;
    __syncthreads();

    int buf = 0;
#pragma unroll 1
    for (int t = 0; t < 16; t++) {
        if (t < 15) {
            int k0 = (t + 1) * 8;
            xv = aok ? *(const float4*)(X + (size_t)arow * HID + k0 + lk) : z4;
            wv = *(const float4*)(W + (size_t)(k0 + wk) * HID + wn);
        }
#pragma unroll
        for (int k = 0; k < 8; k++) {
            ulonglong2 a01 = *(const ulonglong2*)&As[buf][k][ty * 8];
            ulonglong2 a23 = *(const ulonglong2*)&As[buf][k][ty * 8 + 4];
            float4 b0 = *(const float4*)&Bs[buf][k][tx * 8];
            float4 b1 = *(const float4*)&Bs[buf][k][tx * 8 + 4];
            unsigned long long av[4] = {a01.x, a01.y, a23.x, a23.y};
            unsigned long long bd[8] = {dup2(b0.x), dup2(b0.y), dup2(b0.z), dup2(b0.w),
                                        dup2(b1.x), dup2(b1.y), dup2(b1.z), dup2(b1.w)};
#pragma unroll
            for (int i = 0; i < 4; i++)
#pragma unroll
                for (int j = 0; j < 8; j++) ffma2(acc[i][j], av[i], bd[j]);
        }
        if (t < 15) {
            int nb = buf ^ 1;
            As[nb][lk + 0][lr] = xv.x; As[nb][lk + 1][lr] = xv.y;
            As[nb][lk + 2][lr] = xv.z; As[nb][lk + 3][lr] = xv.w;
            *(float4*)&Bs[nb][wk][wn] = wv;
            __syncthreads();
            buf = nb;
        }
    }

    float bcol[8];
#pragma unroll
    for (int j = 0; j < 8; j++) bcol[j] = bias[tx * 8 + j];
#pragma unroll
    for (int i = 0; i < 4; i++) {
        float o0[8], o1[8];
#pragma unroll
        for (int j = 0; j < 8; j++) {
            float2 p = unpk2(acc[i][j]);
            o0[j] = p.x + bcol[j];
            o1[j] = p.y + bcol[j];
        }
        int row0 = rowBase + ty * 8 + i * 2;
        if (row0 < N) {
            float* yp = Y + (size_t)row0 * HID + tx * 8;
            *(float4*)yp = make_float4(o0[0], o0[1], o0[2], o0[3]);
            *(float4*)(yp + 4) = make_float4(o0[4], o0[5], o0[6], o0[7]);
        }
        if (row0 + 1 < N) {
            float* yp = Y + (size_t)(row0 + 1) * HID + tx * 8;
            *(float4*)yp = make_float4(o1[0], o1[1], o1[2], o1[3]);
            *(float4*)(yp + 4) = make_float4(o1[4], o1[5], o1[6], o1[7]);
        }
    }
}

// ---------------- fused GATv2: 4-edge-unrolled online softmax + LN ----------------
__device__ __forceinline__ float edge_score(float4 xl4, float4 xr4, float4 at4) {
    float vx = xl4.x + xr4.x; vx = vx > 0.f ? vx : SLOPE * vx;
    float vy = xl4.y + xr4.y; vy = vy > 0.f ? vy : SLOPE * vy;
    float vz = xl4.z + xr4.z; vz = vz > 0.f ? vz : SLOPE * vz;
    float vw = xl4.w + xr4.w; vw = vw > 0.f ? vw : SLOPE * vw;
    float sc = vx * at4.x + vy * at4.y + vz * at4.z + vw * at4.w;
    sc += __shfl_xor_sync(0xffffffffu, sc, 1);
    sc += __shfl_xor_sync(0xffffffffu, sc, 2);
    sc += __shfl_xor_sync(0xffffffffu, sc, 4);
    return sc;  // per-head score, uniform within each 8-lane group
}

__global__ void gat_kernel(const int* __restrict__ off, const int* __restrict__ csrc,
                           const float* __restrict__ xl, const float* __restrict__ xr,
                           const float* __restrict__ att, const float* __restrict__ bias,
                           const float* __restrict__ lng, const float* __restrict__ lnb,
                           float* __restrict__ x, int n_dst) {
    int d = (blockIdx.x * blockDim.x + threadIdx.x) >> 5;
    if (d >= n_dst) return;
    int l = threadIdx.x & 31;
    int ofs = l * 4;

    float4 xr4 = *(const float4*)(xr + (size_t)d * HID + ofs);
    float4 at4 = *(const float4*)(att + ofs);
    int e0 = off[d], e1 = off[d + 1];

    float m = -1e30f, den = 0.f;
    float4 acc = make_float4(0.f, 0.f, 0.f, 0.f);

    for (int e = e0; e < e1; e += 4) {
        int ns = e1 - e;
        int s0 = csrc[e];
        int s1 = (ns > 1) ? csrc[e + 1] : s0;
        int s2 = (ns > 2) ? csrc[e + 2] : s0;
        int s3 = (ns > 3) ? csrc[e + 3] : s0;
        float4 v0 = *(const float4*)(xl + (size_t)s0 * HID + ofs);
        float4 v1 = *(const float4*)(xl + (size_t)s1 * HID + ofs);
        float4 v2 = *(const float4*)(xl + (size_t)s2 * HID + ofs);
        float4 v3 = *(const float4*)(xl + (size_t)s3 * HID + ofs);
        float sc0 = edge_score(v0, xr4, at4);
        float sc1 = edge_score(v1, xr4, at4);
        float sc2 = edge_score(v2, xr4, at4);
        float sc3 = edge_score(v3, xr4, at4);
        if (ns < 4) sc3 = -1e30f;
        if (ns < 3) sc2 = -1e30f;
        if (ns < 2) sc1 = -1e30f;
        float gm = fmaxf(fmaxf(sc0, sc1), fmaxf(sc2, sc3));
        float nm = fmaxf(m, gm);
        float f = __expf(m - nm);
        float e0x = __expf(sc0 - nm);
        float e1x = __expf(sc1 - nm);
        float e2x = __expf(sc2 - nm);
        float e3x = __expf(sc3 - nm);
        den = den * f + ((e0x + e1x) + (e2x + e3x));
        acc.x = acc.x * f + (fmaf(e0x, v0.x, e1x * v1.x) + fmaf(e2x, v2.x, e3x * v3.x));
        acc.y = acc.y * f + (fmaf(e0x, v0.y, e1x * v1.y) + fmaf(e2x, v2.y, e3x * v3.y));
        acc.z = acc.z * f + (fmaf(e0x, v0.z, e1x * v1.z) + fmaf(e2x, v2.z, e3x * v3.z));
        acc.w = acc.w * f + (fmaf(e0x, v0.w, e1x * v1.w) + fmaf(e2x, v2.w, e3x * v3.w));
        m = nm;
    }

    float inv = (e1 > e0) ? 1.0f / den : 0.0f;
    float4 b4 = *(const float4*)(bias + ofs);
    float4 x4 = *(const float4*)(x + (size_t)d * HID + ofs);
    float4 o;
    o.x = acc.x * inv + b4.x + x4.x;
    o.y = acc.y * inv + b4.y + x4.y;
    o.z = acc.z * inv + b4.z + x4.z;
    o.w = acc.w * inv + b4.w + x4.w;

    float s = o.x + o.y + o.z + o.w;
#pragma unroll
    for (int k = 16; k > 0; k >>= 1) s += __shfl_xor_sync(0xffffffffu, s, k);
    float mu = s * (1.0f / HID);
    float q = (o.x - mu) * (o.x - mu) + (o.y - mu) * (o.y - mu) +
              (o.z - mu) * (o.z - mu) + (o.w - mu) * (o.w - mu);
#pragma unroll
    for (int k = 16; k > 0; k >>= 1) q += __shfl_xor_sync(0xffffffffu, q, k);
    float rs = rsqrtf(q * (1.0f / HID) + LNEPS);
    float4 g4 = *(const float4*)(lng + ofs);
    float4 bb4 = *(const float4*)(lnb + ofs);
    o.x = (o.x - mu) * rs * g4.x + bb4.x;
    o.y = (o.y - mu) * rs * g4.y + bb4.y;
    o.z = (o.z - mu) * rs * g4.z + bb4.z;
    o.w = (o.w - mu) * rs * g4.w + bb4.w;
    *(float4*)(x + (size_t)d * HID + ofs) = o;
}

// ---------------- final column mean ----------------
__global__ void zero_out_kernel(float* __restrict__ out) { out[threadIdx.x] = 0.0f; }

__global__ void colmean_kernel(const float* __restrict__ xc, float* __restrict__ out, int N) {
    int t = threadIdx.x;  // 128
    float s = 0.0f;
    for (int r = blockIdx.x; r < N; r += gridDim.x) s += xc[(size_t)r * HID + t];
    atomicAdd(&out[t], s * (1.0f / N));
}

// ---------------- host orchestration ----------------
static inline int ceil_div(int a, int b) { return (a + b - 1) / b; }

extern "C" void kernel_launch(void* const* d_in, const int* in_sizes, int n_in,
                              void* d_out, int out_size) {
    const float* x_node       = (const float*)d_in[0];
    const float* x_class      = (const float*)d_in[1];
    const int*   member_src   = (const int*)d_in[2];
    const int*   member_dst   = (const int*)d_in[3];
    const int*   contains_src = (const int*)d_in[4];
    const int*   contains_dst = (const int*)d_in[5];
    const float* npw = (const float*)d_in[6];
    const float* npb = (const float*)d_in[7];
    const float* cpw = (const float*)d_in[8];
    const float* cpb = (const float*)d_in[9];
    const float* n2c_wl   = (const float*)d_in[10];
    const float* n2c_bl   = (const float*)d_in[11];
    const float* n2c_wr   = (const float*)d_in[12];
    const float* n2c_br   = (const float*)d_in[13];
    const float* n2c_att  = (const float*)d_in[14];
    const float* n2c_bias = (const float*)d_in[15];
    const float* c2n_wl   = (const float*)d_in[16];
    const float* c2n_bl   = (const float*)d_in[17];
    const float* c2n_wr   = (const float*)d_in[18];
    const float* c2n_br   = (const float*)d_in[19];
    const float* c2n_att  = (const float*)d_in[20];
    const float* c2n_bias = (const float*)d_in[21];
    const float* ln_cg = (const float*)d_in[22];
    const float* ln_cb = (const float*)d_in[23];
    const float* ln_ng = (const float*)d_in[24];
    const float* ln_nb = (const float*)d_in[25];
    float* out = (float*)d_out;

    int E = in_sizes[2];

    float *xn, *xc, *xl, *xr;
    int *deg_m, *cur_m, *deg_c, *cur_c, *off_m, *off_c, *src_m, *src_c, *part;
    cudaGetSymbolAddress((void**)&xn, g_xn);
    cudaGetSymbolAddress((void**)&xc, g_xc);
    cudaGetSymbolAddress((void**)&xl, g_xl);
    cudaGetSymbolAddress((void**)&xr, g_xr);
    cudaGetSymbolAddress((void**)&deg_m, g_deg_m);
    cudaGetSymbolAddress((void**)&cur_m, g_cur_m);
    cudaGetSymbolAddress((void**)&deg_c, g_deg_c);
    cudaGetSymbolAddress((void**)&cur_c, g_cur_c);
    cudaGetSymbolAddress((void**)&off_m, g_off_m);
    cudaGetSymbolAddress((void**)&off_c, g_off_c);
    cudaGetSymbolAddress((void**)&src_m, g_src_m);
    cudaGetSymbolAddress((void**)&src_c, g_src_c);
    cudaGetSymbolAddress((void**)&part, g_part);

    int g2E = ceil_div(2 * E, 256);
    int gNNb = ceil_div(NN, 128);
    int gNCb = ceil_div(NC, 128);

    // 0-3: CSR build (deg + chunk sums + bases)
    build_zero_kernel<<<ceil_div(NN, 256), 256>>>(deg_m, deg_c);
    build_hist_kernel<<<g2E, 256>>>(member_dst, contains_dst, deg_m, deg_c, E);
    scanA_kernel<<<NB_T, 256>>>(deg_m, deg_c, part);
    scanB_kernel<<<1, 128>>>(part, off_m, off_c, E);
    // 4: input projections (independent of CSR)
    proj_both_kernel<<<NN + NC, 128>>>(x_node, npw, npb, xn, x_class, cpw, cpb, xc);
    // 5: first dual GEMM (profiled by ncu -s 5 -c 1)
    sgemm128_dual<<<gNNb + gNCb, 256>>>(xn, n2c_wl, n2c_bl, xl, NN, gNNb,
                                        xc, n2c_wr, n2c_br, xr, NC);
    // 6-7: finish CSR (offsets + scatter)
    scanC_kernel<<<NB_T, 256>>>(deg_m, deg_c, part, off_m, off_c, cur_m, cur_c);
    build_scatter_kernel<<<g2E, 256>>>(member_src, member_dst, contains_src, contains_dst,
                                       cur_m, cur_c, src_m, src_c, E);

    for (int l = 0; l < NL; l++) {
        if (l > 0) {
            sgemm128_dual<<<gNNb + gNCb, 256>>>(xn, n2c_wl + (size_t)l * HID * HID,
                                                n2c_bl + l * HID, xl, NN, gNNb,
                                                xc, n2c_wr + (size_t)l * HID * HID,
                                                n2c_br + l * HID, xr, NC);
        }
        gat_kernel<<<ceil_div(NC * 32, 256), 256>>>(off_m, src_m, xl, xr,
                                                    n2c_att + l * HID, n2c_bias + l * HID,
                                                    ln_cg + l * HID, ln_cb + l * HID,
                                                    xc, NC);
        sgemm128_dual<<<gNCb + gNNb, 256>>>(xc, c2n_wl + (size_t)l * HID * HID,
                                            c2n_bl + l * HID, xl, NC, gNCb,
                                            xn, c2n_wr + (size_t)l * HID * HID,
                                            c2n_br + l * HID, xr, NN);
        gat_kernel<<<ceil_div(NN * 32, 256), 256>>>(off_c, src_c, xl, xr,
                                                    c2n_att + l * HID, c2n_bias + l * HID,
                                                    ln_ng + l * HID, ln_nb + l * HID,
                                                    xn, NN);
    }

    // final: out = mean over rows of xc
    zero_out_kernel<<<1, 128>>>(out);
    colmean_kernel<<<256, 128>>>(xc, out, NC);
}